// round 12
// baseline (speedup 1.0000x reference)
#include <cuda_runtime.h>

#define BN   8
#define CN   64
#define HN   256
#define WN   256
#define HP   257
#define WP   257
#define HWN  (HN * WN)          // 65536
#define NPIX (HP * WP)          // 66049
#define LN_EPS 1e-5f
#define NEG_SLOPE 0.01f

// Padded channel-sum plane: cs(h,w) stored at [(h+3)*CST + (w+4)].
// 262 rows (cs rows -3..258), stride 268 (cols -4..263). Border is zero
// (zero-initialized device globals; interior-only writes). Composed 6x6
// stencil taps (rows/cols -3..+2) never leave the plane.
#define CROWS 262
#define CST   268
#define CPLANE (CROWS * CST)

#define NBLK  65                // downstream blocks per image
#define NGRID (NBLK * BN)       // 520 blocks, single resident wave
#define NTHR  256
#define Q4    (HWN / 4)         // 16384 float4 columns per image plane

// Scratch (static device globals — allowed)
__device__ float g_csp[BN * CPLANE];       // padded channel sum (~2.25 MB)
__device__ float g_part[BN * NBLK * 2];    // per-block (sum, sumsq)
__device__ unsigned int g_cs_tkt[BN * 32]; // per-image chansum counters (128B
                                           // apart). Monotone: +NGRID/launch.
__device__ unsigned int g_pt_tkt[BN * 32]; // per-image partials counters.
                                           // Monotone: +NBLK/launch.
// Both counters advance by exact multiples per launch -> value is the right
// multiple at every launch start => CUDA-graph replay safe, no resets.

// ---------------------------------------------------------------------------
// One persistent kernel, image-pipelined:
//   for i = 0..7: all 520 blocks sum a 1/520 slice of image i's channels;
//   when i == own image: wait cs counter -> stencil + partials -> wait pt
//   counter -> stats + normalize + LeakyReLU; then continue chansum.
// Downstream of images 0..6 overlaps the remaining chansum DRAM traffic.
// ---------------------------------------------------------------------------
__global__ void __launch_bounds__(NTHR, 4)
k_all(const float* __restrict__ x, const float* __restrict__ cw,
      const float* __restrict__ cb, float* __restrict__ out) {
    __shared__ float  s_c6[36];               // composed 6x6 stencil coeffs
    __shared__ float  s_tile[10 * CST];       // 10 padded rows (10.5 KB)
    __shared__ float  s_red[8][2];
    __shared__ float4 s_acc[NTHR];            // chansum cross-group partials

    const int tid   = threadIdx.x;
    const int blk   = blockIdx.x;
    const int b_own = blk / NBLK;             // image this block post-processes
    const int xb    = blk - b_own * NBLK;     // index within image [0,65)

    // ---- Composed coefficients: pool(2) o 16-tap shift stencil = 6x6 ----
    if (tid < 36) {
        const signed char tdr[16] = {2,-2, 2,-2, 2,-2, 2,-2, 2,-2, 1,-1, 0,0, -1,1};
        const signed char tdc[16] = {2,-2, 1,-1, 0, 0,-1, 1,-2, 2,-2, 2,-2,2, -2,2};
        const signed char twi[16] = {0, 0, 1, 1, 2, 2, 3, 3, 4, 4, 5, 5, 6,6,  7,7};
        const signed char tsg[16] = {1,-1, 1,-1, 1,-1, 1,-1, 1,-1, 1,-1, 1,-1, 1,-1};
        int r = tid / 6 - 3, c = tid % 6 - 3;
        float acc = 0.f;
        for (int t2 = 0; t2 < 16; ++t2) {
            int ur = r - tdr[t2], uc = c - tdc[t2];
            if ((ur == 0 || ur == -1) && (uc == 0 || uc == -1))
                acc += (float)tsg[t2] * cw[twi[t2]];
        }
        s_c6[tid] = 0.25f * acc;
    }

    // Chansum slice geometry (identical for every image): block handles
    // float4 columns [blk*Q4/520, (blk+1)*Q4/520) -> 31 or 32 columns.
    // Threads: 32 columns x 8 channel-groups (8 channels each).
    const unsigned cbase = ((unsigned)blk * Q4) / NGRID;
    const unsigned cend  = ((unsigned)(blk + 1) * Q4) / NGRID;
    const int ncols = (int)(cend - cbase);
    const int ci = tid & 31;                  // column within slice
    const int cg = tid >> 5;                  // channel group (8 channels)

    // Phase B/C geometry (R8/R11 layout: 1024-px chunk, 4 strided px/thread)
    const int p0    = xb * 1024;
    const int pend  = (p0 + 1024 < NPIX) ? p0 + 1024 : NPIX;
    const int pbase = p0 + tid;
    const float bias = __ldg(cb);

    for (int i = 0; i < BN; ++i) {
        // ---- chansum slice for image i ----
        float4 a = make_float4(0.f, 0.f, 0.f, 0.f);
        if (ci < ncols) {
            const float4* xp = reinterpret_cast<const float4*>(x)
                               + ((size_t)i * CN + (size_t)cg * 8) * Q4
                               + cbase + ci;
            float4 buf[8];
#pragma unroll
            for (int k = 0; k < 8; ++k)
                buf[k] = __ldcs(xp + (size_t)k * Q4);
#pragma unroll
            for (int k = 0; k < 8; ++k) {
                a.x += buf[k].x; a.y += buf[k].y; a.z += buf[k].z; a.w += buf[k].w;
            }
        }
        s_acc[tid] = a;
        __syncthreads();
        if (tid < 32 && tid < ncols) {
            float4 s = s_acc[tid];
#pragma unroll
            for (int g = 1; g < 8; ++g) {            // fixed order: deterministic
                float4 t4 = s_acc[tid + 32 * g];
                s.x += t4.x; s.y += t4.y; s.z += t4.z; s.w += t4.w;
            }
            int p = (int)(cbase + tid) * 4;
            int h = p >> 8, w = p & 255;
            *reinterpret_cast<float4*>(
                g_csp + (size_t)i * CPLANE + (h + 3) * CST + (w + 4)) = s;
        }
        __syncthreads();                     // s_acc reusable; s_c6 visible

        unsigned tkt = 0;
        if (tid == 0) {
            __threadfence();                 // publish plane stores
            tkt = atomicAdd(&g_cs_tkt[i * 32], 1u) + 1u;
        }

        if (i == b_own) {
            // ---- wait: image b_own's plane complete (all 520 slices) ----
            if (tid == 0) {
                unsigned target = ((tkt + NGRID - 1u) / NGRID) * NGRID;
                volatile unsigned* vc = &g_cs_tkt[i * 32];
                while (*vc < target) __nanosleep(32);
            }
            __syncthreads();
            __threadfence();                 // acquire peers' plane stores

            // ---- Phase B: 36-tap stencil from smem tile ----
            const int h0 = p0 / WP;
            const float* __restrict__ plane = g_csp + (size_t)b_own * CPLANE;
            for (int i4 = tid; i4 < 10 * (CST / 4); i4 += NTHR) {
                int r  = i4 / (CST / 4);
                int c4 = i4 - r * (CST / 4);
                int pr = h0 + r;
                float4 v = make_float4(0.f, 0.f, 0.f, 0.f);
                if (pr < CROWS)
                    v = *(reinterpret_cast<const float4*>(
                            plane + (size_t)pr * CST) + c4);
                reinterpret_cast<float4*>(s_tile)[i4] = v;
            }
            __syncthreads();

            float vv[4];
            float lsum = 0.f, lsq = 0.f;
            int  hh[4], jj[4];
            bool ok[4];
#pragma unroll
            for (int k = 0; k < 4; ++k) {
                int p = pbase + k * 256;
                ok[k] = p < pend;
                int h = p / WP;
                hh[k] = h; jj[k] = p - h * WP;
                vv[k] = bias;
            }
#pragma unroll
            for (int r = 0; r < 6; ++r) {
#pragma unroll
                for (int c = 0; c < 6; ++c) {
                    float cf = s_c6[r * 6 + c];
#pragma unroll
                    for (int k = 0; k < 4; ++k)
                        if (ok[k])
                            vv[k] = fmaf(cf,
                                s_tile[(hh[k] - h0 + r) * CST + jj[k] + 1 + c],
                                vv[k]);
                }
            }
#pragma unroll
            for (int k = 0; k < 4; ++k)
                if (ok[k]) { lsum += vv[k]; lsq += vv[k] * vv[k]; }

            // Deterministic block reduction
#pragma unroll
            for (int o = 16; o > 0; o >>= 1) {
                lsum += __shfl_down_sync(0xffffffffu, lsum, o);
                lsq  += __shfl_down_sync(0xffffffffu, lsq,  o);
            }
            int wid = tid >> 5, lane = tid & 31;
            if (lane == 0) { s_red[wid][0] = lsum; s_red[wid][1] = lsq; }
            __syncthreads();
            if (tid == 0) {
                float aa = 0.f, qq = 0.f;
#pragma unroll
                for (int w2 = 0; w2 < 8; ++w2) {
                    aa += s_red[w2][0]; qq += s_red[w2][1];
                }
                g_part[(b_own * NBLK + xb) * 2 + 0] = aa;
                g_part[(b_own * NBLK + xb) * 2 + 1] = qq;
                __threadfence();             // publish partials
                unsigned pt = atomicAdd(&g_pt_tkt[b_own * 32], 1u) + 1u;
                unsigned target = ((pt + NBLK - 1u) / NBLK) * NBLK;
                volatile unsigned* vp = &g_pt_tkt[b_own * 32];
                while (*vp < target) __nanosleep(32);   // peers run concurrently
            }
            __syncthreads();
            __threadfence();                 // acquire peers' partials

            // ---- Phase C: redundant deterministic stats + norm + LeakyReLU ----
            const float* __restrict__ part = g_part + b_own * NBLK * 2;
            float aa = 0.f, qq = 0.f;
#pragma unroll
            for (int ii = 0; ii < NBLK; ++ii) {
                aa += part[ii * 2 + 0];
                qq += part[ii * 2 + 1];
            }
            const float inv_n = 1.0f / (float)NPIX;
            const float mean = aa * inv_n;
            const float istd = rsqrtf(qq * inv_n - mean * mean + LN_EPS);

            float* __restrict__ o = out + (size_t)b_own * NPIX;
#pragma unroll
            for (int k = 0; k < 4; ++k) {
                int p = pbase + k * 256;
                if (p < pend) {
                    float v = (vv[k] - mean) * istd;
                    o[p] = v >= 0.f ? v : NEG_SLOPE * v;
                }
            }
            __syncthreads();                 // done with s_tile before loop cont.
        }
    }
}

// ---------------------------------------------------------------------------

extern "C" void kernel_launch(void* const* d_in, const int* in_sizes, int n_in,
                              void* d_out, int out_size) {
    const float* x  = (const float*)d_in[0];   // [8,64,256,256]
    const float* cw = (const float*)d_in[1];   // [1,8]
    const float* cb = (const float*)d_in[2];   // [1]
    float* out = (float*)d_out;                // [8,1,257,257]
    (void)in_sizes; (void)n_in; (void)out_size;

    k_all<<<NGRID, NTHR>>>(x, cw, cb, out);
}

// round 13
// speedup vs baseline: 2.0308x; 2.0308x over previous
#include <cuda_runtime.h>

#define BN   8
#define CN   64
#define HN   256
#define WN   256
#define HP   257
#define WP   257
#define HWN  (HN * WN)          // 65536
#define NPIX (HP * WP)          // 66049
#define LN_EPS 1e-5f
#define NEG_SLOPE 0.01f

// Padded channel-sum plane: cs(h,w) stored at [(h+3)*CST + (w+4)].
// 262 rows (cs rows -3..258), stride 268 (cols -4..263). Border is zero
// (zero-initialized device globals; interior-only writes). Composed 6x6
// stencil taps (rows/cols -3..+2) never leave the plane.
#define CROWS 262
#define CST   268
#define CPLANE (CROWS * CST)

#define NBLK  74                // blocks per image
#define NGRID (NBLK * BN)       // 592 = 4 * 148 SMs -> exact balanced wave
#define NTHR  256
#define CHUNK 893               // pixels per chunk (74*893 = 66082 >= 66049)
#define Q4    (HWN / 4)         // 16384 float4 columns per image plane

// Scratch (static device globals — allowed)
__device__ float g_csp[BN * CPLANE];       // padded channel sum (~2.25 MB)
__device__ float g_part[BN * NBLK * 2];    // per-block (sum, sumsq)
__device__ unsigned int g_tkt[BN * 32];    // per-image ticket counters, 128B
                                           // apart; monotone (each launch adds
                                           // exactly 2*NBLK per image -> value
                                           // is a multiple of NBLK at launch
                                           // start => graph-replay safe)

// ---------------------------------------------------------------------------
// Per-image ticket barrier: only the 74 blocks of one image synchronize, so
// an image whose producers finished proceeds without waiting for the global
// tail. Exact single wave (592 = 4*148, launch_bounds(256,4)) => spin safe.
// ---------------------------------------------------------------------------
__device__ __forceinline__ void img_barrier(int tid, int b) {
    __syncthreads();
    if (tid == 0) {
        __threadfence();                              // publish this block's stores
        unsigned* c = &g_tkt[b * 32];
        unsigned t = atomicAdd(c, 1u) + 1u;
        unsigned target = ((t + NBLK - 1u) / NBLK) * NBLK;
        volatile unsigned* vc = c;
        while (*vc < target) __nanosleep(32);
    }
    __syncthreads();
    __threadfence();                                  // acquire peers' stores
}

// ---------------------------------------------------------------------------
// One persistent kernel: image-local chansum (full-depth 64-channel loops,
// NO intra-phase syncs) -> per-image barrier -> 36-tap composed stencil
// (+ LN partials) -> per-image barrier -> stats + normalize + LeakyReLU.
// ---------------------------------------------------------------------------
__global__ void __launch_bounds__(NTHR, 4)
k_all(const float* __restrict__ x, const float* __restrict__ cw,
      const float* __restrict__ cb, float* __restrict__ out) {
    __shared__ float s_c6[36];                // composed 6x6 stencil coeffs
    __shared__ float s_tile[10 * CST];        // 10 padded rows (10.5 KB)
    __shared__ float s_red[8][2];

    const int tid = threadIdx.x;
    const int blk = blockIdx.x;
    const int b   = blk / NBLK;               // this block's image
    const int xb  = blk - b * NBLK;           // index within image [0,74)

    // ---- Phase 0: channel sum for image b only (image-local columns) ----
    // Block xb handles float4 columns [xb*Q4/74, (xb+1)*Q4/74): 221-222,
    // one per thread, 64 channels deep with 8-deep load batching.
    {
        unsigned base = ((unsigned)xb * Q4) / NBLK;
        unsigned end  = ((unsigned)(xb + 1) * Q4) / NBLK;
        unsigned col  = base + (unsigned)tid;
        if (col < end) {
            const float4* xp = reinterpret_cast<const float4*>(x)
                               + (size_t)b * CN * Q4 + col;
            float ax = 0.f, ay = 0.f, az = 0.f, aw = 0.f;
#pragma unroll
            for (int cc = 0; cc < CN; cc += 8) {
                float4 buf[8];
#pragma unroll
                for (int i = 0; i < 8; ++i)
                    buf[i] = __ldcs(xp + (size_t)(cc + i) * Q4);
#pragma unroll
                for (int i = 0; i < 8; ++i) {
                    ax += buf[i].x; ay += buf[i].y; az += buf[i].z; aw += buf[i].w;
                }
            }
            int p = (int)col * 4;
            int h = p >> 8, w = p & 255;
            *reinterpret_cast<float4*>(
                g_csp + (size_t)b * CPLANE + (h + 3) * CST + (w + 4)) =
                make_float4(ax, ay, az, aw);
        }
    }

    // ---- Composed coefficients: pool(2) o 16-tap shift stencil = 6x6 ----
    if (tid < 36) {
        const signed char tdr[16] = {2,-2, 2,-2, 2,-2, 2,-2, 2,-2, 1,-1, 0,0, -1,1};
        const signed char tdc[16] = {2,-2, 1,-1, 0, 0,-1, 1,-2, 2,-2, 2,-2,2, -2,2};
        const signed char twi[16] = {0, 0, 1, 1, 2, 2, 3, 3, 4, 4, 5, 5, 6,6,  7,7};
        const signed char tsg[16] = {1,-1, 1,-1, 1,-1, 1,-1, 1,-1, 1,-1, 1,-1, 1,-1};
        int r = tid / 6 - 3, c = tid % 6 - 3;
        float acc = 0.f;
        for (int t2 = 0; t2 < 16; ++t2) {
            int ur = r - tdr[t2], uc = c - tdc[t2];
            if ((ur == 0 || ur == -1) && (uc == 0 || uc == -1))
                acc += (float)tsg[t2] * cw[twi[t2]];
        }
        s_c6[tid] = 0.25f * acc;
    }

    img_barrier(tid, b);                      // image b's cs plane ready

    // ---- Phase B: 36-tap stencil from smem tile (893-px chunk, 4 strided
    //      pixels per thread) ----
    const int p0   = xb * CHUNK;
    const int pend = (p0 + CHUNK < NPIX) ? p0 + CHUNK : NPIX;
    const int h0   = p0 / WP;                 // first output row of this chunk
    const float* __restrict__ plane = g_csp + (size_t)b * CPLANE;

    // Tile = padded rows h0..h0+9 (covers taps for output rows h0..h0+4).
    for (int i4 = tid; i4 < 10 * (CST / 4); i4 += NTHR) {
        int r  = i4 / (CST / 4);
        int c4 = i4 - r * (CST / 4);
        int pr = h0 + r;
        float4 v = make_float4(0.f, 0.f, 0.f, 0.f);
        if (pr < CROWS)
            v = *(reinterpret_cast<const float4*>(plane + (size_t)pr * CST) + c4);
        reinterpret_cast<float4*>(s_tile)[r * (CST / 4) + c4] = v;
    }
    __syncthreads();

    const float bias = __ldg(cb);
    float vv[4] = {0.f, 0.f, 0.f, 0.f};
    float lsum = 0.f, lsq = 0.f;
    const int pbase = p0 + tid;
    {
        int  hh[4], jj[4];
        bool ok[4];
#pragma unroll
        for (int k = 0; k < 4; ++k) {
            int p = pbase + k * 256;
            ok[k] = p < pend;
            int h = p / WP;
            hh[k] = h; jj[k] = p - h * WP;
            vv[k] = bias;
        }
        // coeff-outer order: one coeff LDS feeds 4 FMAs
#pragma unroll
        for (int r = 0; r < 6; ++r) {
#pragma unroll
            for (int c = 0; c < 6; ++c) {
                float cf = s_c6[r * 6 + c];
#pragma unroll
                for (int k = 0; k < 4; ++k)
                    if (ok[k])
                        vv[k] = fmaf(cf,
                                     s_tile[(hh[k] - h0 + r) * CST + jj[k] + 1 + c],
                                     vv[k]);
            }
        }
#pragma unroll
        for (int k = 0; k < 4; ++k)
            if (ok[k]) { lsum += vv[k]; lsq += vv[k] * vv[k]; }
    }

    // Deterministic block reduction
#pragma unroll
    for (int o = 16; o > 0; o >>= 1) {
        lsum += __shfl_down_sync(0xffffffffu, lsum, o);
        lsq  += __shfl_down_sync(0xffffffffu, lsq,  o);
    }
    int wid = tid >> 5, lane = tid & 31;
    if (lane == 0) { s_red[wid][0] = lsum; s_red[wid][1] = lsq; }
    __syncthreads();
    if (tid == 0) {
        float a = 0.f, q = 0.f;
#pragma unroll
        for (int w = 0; w < 8; ++w) { a += s_red[w][0]; q += s_red[w][1]; }
        g_part[(b * NBLK + xb) * 2 + 0] = a;
        g_part[(b * NBLK + xb) * 2 + 1] = q;
    }

    img_barrier(tid, b);                      // image b's partials ready

    // ---- Phase C: redundant deterministic stats + normalize + LeakyReLU ----
    const float* __restrict__ part = g_part + b * NBLK * 2;
    float a = 0.f, q = 0.f;
#pragma unroll
    for (int i = 0; i < NBLK; ++i) {
        a += part[i * 2 + 0];
        q += part[i * 2 + 1];
    }
    const float inv_n = 1.0f / (float)NPIX;
    const float mean = a * inv_n;
    const float istd = rsqrtf(q * inv_n - mean * mean + LN_EPS);

    float* __restrict__ o = out + (size_t)b * NPIX;
#pragma unroll
    for (int k = 0; k < 4; ++k) {
        int p = pbase + k * 256;
        if (p < pend) {
            float v = (vv[k] - mean) * istd;
            o[p] = v >= 0.f ? v : NEG_SLOPE * v;
        }
    }
}

// ---------------------------------------------------------------------------

extern "C" void kernel_launch(void* const* d_in, const int* in_sizes, int n_in,
                              void* d_out, int out_size) {
    const float* x  = (const float*)d_in[0];   // [8,64,256,256]
    const float* cw = (const float*)d_in[1];   // [1,8]
    const float* cb = (const float*)d_in[2];   // [1]
    float* out = (float*)d_out;                // [8,1,257,257]
    (void)in_sizes; (void)n_in; (void)out_size;

    k_all<<<NGRID, NTHR>>>(x, cw, cb, out);
}